// round 9
// baseline (speedup 1.0000x reference)
#include <cuda_runtime.h>
#include <cstddef>

// Problem constants (from reference setup_inputs)
#define TT   1000
#define BB   8192
#define IN   4
#define HID  10
#define OUT  3
#define BETA 0.95f
#define THR  1.0f

#define NLUT (1 << HID)      // 1024 possible spk1 patterns
#define B3   (BB * OUT)      // floats per timestep per output array
#define HHALF 5              // hidden units per thread-half

// Two threads per batch element. 128 blocks x 128 threads = 16384 threads.
// Even lane = half 0 (units 0-4, writes spk2), odd lane = half 1 (units 5-9,
// writes mem2). Software-pipelined: layer-1 of step t+1 overlaps the
// shfl+LUT+layer-2 of step t.
__global__ __launch_bounds__(128, 1)
void snn_lif_kernel(const float* __restrict__ x,
                    const float* __restrict__ W1,
                    const float* __restrict__ b1,
                    const float* __restrict__ W2,
                    const float* __restrict__ b2,
                    float* __restrict__ out)
{
    // LUT: cur2 = W2 @ spk1 + b2 for every possible spk1 bitmask.
    // Ascending-h subset sum, separately-rounded adds, bias last —
    // bit-identical to the reference 0/1 dot under fma OR mul+add lowering.
    __shared__ float4 lut[NLUT];
    for (int m = threadIdx.x; m < NLUT; m += blockDim.x) {
        float c0 = 0.f, c1 = 0.f, c2 = 0.f;
        #pragma unroll
        for (int h = 0; h < HID; ++h) {
            if (m & (1 << h)) {
                c0 = __fadd_rn(c0, W2[0 * HID + h]);
                c1 = __fadd_rn(c1, W2[1 * HID + h]);
                c2 = __fadd_rn(c2, W2[2 * HID + h]);
            }
        }
        c0 = __fadd_rn(c0, b2[0]);
        c1 = __fadd_rn(c1, b2[1]);
        c2 = __fadd_rn(c2, b2[2]);
        lut[m] = make_float4(c0, c1, c2, 0.f);
    }

    const int tid   = blockIdx.x * blockDim.x + threadIdx.x;
    const int e     = tid >> 1;        // batch element
    const int half  = tid & 1;         // which 5 hidden units
    const int hbase = half * HHALF;

    // This half's layer-1 weights in registers (20 + 5 floats).
    float w1[HHALF][IN], bb1[HHALF];
    #pragma unroll
    for (int j = 0; j < HHALF; ++j) {
        bb1[j] = b1[hbase + j];
        #pragma unroll
        for (int i = 0; i < IN; ++i) w1[j][i] = W1[(hbase + j) * IN + i];
    }
    __syncthreads();

    // State: membranes + prev-spike stored as float in {-1, 0} so reset is a
    // single always-executed add (adding -0.0f is the identity => bit-exact).
    float m1[HHALF], s1[HHALF];
    float m2[OUT],   s2[OUT];
    #pragma unroll
    for (int j = 0; j < HHALF; ++j) { m1[j] = 0.f; s1[j] = 0.f; }
    #pragma unroll
    for (int o = 0; o < OUT; ++o)   { m2[o] = 0.f; s2[o] = 0.f; }

    const float4* __restrict__ xp = reinterpret_cast<const float4*>(x) + e;
    // half 0 -> spk2_rec (offset 0), half 1 -> mem2_rec (offset TT*B3).
    float* __restrict__ po = out + (size_t)half * TT * B3 + (size_t)e * OUT;

    // Prefetch ring: x[t..t+3] resident.
    float4 xbuf[4];
    #pragma unroll
    for (int k = 0; k < 4; ++k) xbuf[k] = xp[(size_t)k * BB];

    // Layer-1 for one step: updates m1/s1, returns this half's mask bits.
    auto layer1 = [&](const float4 xv) -> unsigned {
        unsigned mk = 0;
        #pragma unroll
        for (int j = 0; j < HHALF; ++j) {
            // Ascending-k, separate mul/add roundings (no fma), bias last.
            float c = __fmul_rn(xv.x, w1[j][0]);
            c = __fadd_rn(c, __fmul_rn(xv.y, w1[j][1]));
            c = __fadd_rn(c, __fmul_rn(xv.z, w1[j][2]));
            c = __fadd_rn(c, __fmul_rn(xv.w, w1[j][3]));
            c = __fadd_rn(c, bb1[j]);
            float m = __fadd_rn(__fmul_rn(BETA, m1[j]), c); // beta*mem + cur
            m = __fadd_rn(m, s1[j]);                         // + (-reset*THR)
            const bool sp = m > THR;
            s1[j] = sp ? -1.0f : 0.0f;                       // pred-as-data SEL
            mk |= (sp ? (1u << (hbase + j)) : 0u);           // pred-as-data SEL
            m1[j] = m;
        }
        return mk;
    };

    // Pipeline prologue: layer-1 of step 0.
    unsigned myMask = layer1(xbuf[0]);

    for (int t = 0; t < TT; t += 4) {
        // Prefetch x[t+4..t+7] (tail clamps to x[0..3]; values feed only the
        // discarded junk layer-1 past step TT-1).
        const float4* xq = (t + 4 < TT) ? (xp + (size_t)(t + 4) * BB) : xp;
        float4 nxt[4];
        #pragma unroll
        for (int k = 0; k < 4; ++k) nxt[k] = xq[(size_t)k * BB];

        #pragma unroll
        for (int k = 0; k < 4; ++k) {
            // ---- step t+k: exchange masks first (26-cyc shfl in flight) ----
            const unsigned fullMask =
                myMask | __shfl_xor_sync(0xFFFFFFFFu, myMask, 1);

            // ---- layer-1 of step t+k+1 overlaps the shfl/LDS latency ----
            const float4 xnext = (k < 3) ? xbuf[k + 1] : nxt[0];
            const unsigned newMask = layer1(xnext);

            // ---- layer-2 of step t+k ----
            const float4 cv = lut[fullMask];
            const float cc[OUT] = { cv.x, cv.y, cv.z };
            float* pk = po + (size_t)(t + k) * B3;
            #pragma unroll
            for (int o = 0; o < OUT; ++o) {
                float m = __fadd_rn(__fmul_rn(BETA, m2[o]), cc[o]);
                m = __fadd_rn(m, s2[o]);
                const bool sp = m > THR;
                s2[o] = sp ? -1.0f : 0.0f;
                m2[o] = m;
                pk[o] = half ? m : (sp ? 1.0f : 0.0f);
            }

            myMask = newMask;
        }

        #pragma unroll
        for (int k = 0; k < 4; ++k) xbuf[k] = nxt[k];
    }
}

extern "C" void kernel_launch(void* const* d_in, const int* in_sizes, int n_in,
                              void* d_out, int out_size)
{
    const float* x  = (const float*)d_in[0];   // [1000, 8192, 4]
    const float* W1 = (const float*)d_in[1];   // [10, 4]
    const float* b1 = (const float*)d_in[2];   // [10]
    const float* W2 = (const float*)d_in[3];   // [3, 10]
    const float* b2 = (const float*)d_in[4];   // [3]
    float* out = (float*)d_out;                // [spk2_rec | mem2_rec]

    snn_lif_kernel<<<(BB * 2) / 128, 128>>>(x, W1, b1, W2, b2, out);
}